// round 12
// baseline (speedup 1.0000x reference)
#include <cuda_runtime.h>

#define HOPS 512
#define NHARM 100
#define TT 400
#define NHALF 50
#define NPAIR 25
#define KSTEPS 16   // window samples per lane (half window per warp)
#define NREGION 2   // regions per block (single-wave persistent grid)

typedef unsigned long long ull;

#define SIGN64 0x8000000080000000ull

// ---- packed f32x2 helpers (sm_103a) ----
__device__ __forceinline__ ull pack2(float lo, float hi) {
    ull r; asm("mov.b64 %0, {%1, %2};" : "=l"(r) : "f"(lo), "f"(hi)); return r;
}
__device__ __forceinline__ void unpack2(ull v, float& lo, float& hi) {
    asm("mov.b64 {%0, %1}, %2;" : "=f"(lo), "=f"(hi) : "l"(v));
}
__device__ __forceinline__ ull fma2(ull a, ull b, ull c) {
    ull d; asm("fma.rn.f32x2 %0, %1, %2, %3;" : "=l"(d) : "l"(a), "l"(b), "l"(c)); return d;
}
__device__ __forceinline__ ull add2(ull a, ull b) {
    ull d; asm("add.rn.f32x2 %0, %1, %2;" : "=l"(d) : "l"(a), "l"(b)); return d;
}
__device__ __forceinline__ ull mul2(ull a, ull b) {
    ull d; asm("mul.rn.f32x2 %0, %1, %2;" : "=l"(d) : "l"(a), "l"(b)); return d;
}

struct Chain { ull p_prev, p_cur, rp, rn; };

// R7-exact seed: theta and theta-D via two fma2 against different wpos
// constants; r = 2cos(32*delta) precomputed in shared; negations are
// 64-bit XORs. (Codegen-fragile — do not restructure; R8/R9 regressed.)
__device__ __forceinline__ Chain seed_pair(ull dd, ull pp, ull aa, ull rp,
                                           ull wpos2, ull wm2) {
    ull x2  = fma2(wpos2, dd, pp);            // theta
    ull xm2 = fma2(wm2,   dd, pp);            // theta - D
    float xA, xB, mA, mB;
    unpack2(x2, xA, xB);
    unpack2(xm2, mA, mB);
    ull cth2  = pack2(__cosf(xA), __cosf(xB));
    ull cthm2 = pack2(__cosf(mA), __cosf(mB));

    Chain c;
    c.p_cur  = mul2(aa, cth2);                // +a*cos(th)
    c.p_prev = mul2(aa ^ SIGN64, cthm2);      // -a*cos(th-D)
    c.rp = rp;                                // +2cos(D) (precomputed)
    c.rn = rp ^ SIGN64;                       // -2cos(D)
    return c;
}

// Single-wave persistent grid: 800 blocks (all resident at once), each
// processing NREGION=2 output regions sequentially — kills the 1.54-wave
// tail that capped issue at ~55% for rounds 2..11.
// Per region: block covers out[r*512,(r+1)*512) of batch b; contributors are
// frame t=r (window half 1) and t=r+1 (window half 0). 4 warps = 2 frames x
// 2 harmonic halves; lane l owns region samples s = l + 32k, k=0..15.
// Dual packed Chebyshev chains, seeds software-pipelined one pair ahead;
// Hann via stride-32 Chebyshev recurrence with an immediate multiplier.
__global__ __launch_bounds__(128, 7) void sinstack_kernel(
    const float* __restrict__ ampl,
    const float* __restrict__ phase,
    const float* __restrict__ f0,
    float* __restrict__ out)
{
    __shared__ ull sh_d2[4][NPAIR];
    __shared__ ull sh_p2[4][NPAIR];
    __shared__ ull sh_a2[4][NPAIR];
    __shared__ ull sh_r2[4][NPAIR];     // 2*cos(32*delta), precomputed
    __shared__ float sh_part[4][512];

    const int warp = threadIdx.x >> 5;
    const int lane = threadIdx.x & 31;

    #pragma unroll 1
    for (int rep = 0; rep < NREGION; rep++) {
        const int fid = blockIdx.x + rep * 800;   // flattened region 0..1599
        const int b = fid / TT;
        const int r = fid - b * TT;               // output region 0..399
        const int wh = 1 - (warp >> 1);           // warps 0,1: frame r; 2,3: frame r+1
        const int hh = warp & 1;                  // harmonic half
        const int t  = r + (warp >> 1);           // frame index (may be TT: dead warp)
        const bool alive = (t < TT);

        if (alive) {
            const float K2PI_SR = 6.283185307179586f / 44100.0f;
            const int base = b * NHARM * TT + (hh * NHALF) * TT + t;
            float* fd = (float*)&sh_d2[warp][0];
            float* fp = (float*)&sh_p2[warp][0];
            float* fa = (float*)&sh_a2[warp][0];
            float* fr = (float*)&sh_r2[warp][0];
            for (int j = lane; j < NHALF; j += 32) {
                int idx = base + j * TT;
                float d = f0[idx] * K2PI_SR;
                fd[j] = d;
                fp[j] = phase[idx];
                fa[j] = ampl[idx];
                fr[j] = 2.0f * __cosf(32.0f * d);   // one-time MUFU, off hot path
            }
        }
        __syncwarp();

        ull acc[KSTEPS];
        #pragma unroll
        for (int k = 0; k < KSTEPS; k++) acc[k] = 0ull;

        if (alive) {
            // window position of lane's k=0 sample: wh=1 -> lane; wh=0 -> lane-512
            const float wpos = (float)(lane + (wh ? 0 : -HOPS));
            const ull wpos2 = pack2(wpos, wpos);
            const ull wm2   = pack2(wpos - 32.0f, wpos - 32.0f);

            Chain A = seed_pair(sh_d2[warp][0], sh_p2[warp][0], sh_a2[warp][0],
                                sh_r2[warp][0], wpos2, wm2);
            Chain B = seed_pair(sh_d2[warp][1], sh_p2[warp][1], sh_a2[warp][1],
                                sh_r2[warp][1], wpos2, wm2);

            #pragma unroll 1
            for (int q = 0; q < 11; q++) {
                int j = 2 * q + 2;
                Chain An = seed_pair(sh_d2[warp][j], sh_p2[warp][j], sh_a2[warp][j],
                                     sh_r2[warp][j], wpos2, wm2);
                Chain Bn = seed_pair(sh_d2[warp][j+1], sh_p2[warp][j+1], sh_a2[warp][j+1],
                                     sh_r2[warp][j+1], wpos2, wm2);
                #pragma unroll
                for (int k = 0; k < KSTEPS; k++) {
                    acc[k] = add2(acc[k], A.p_cur);
                    acc[k] = add2(acc[k], B.p_cur);
                    ull nA = fma2(((k + 1) & 1) ? A.rp : A.rn, A.p_cur, A.p_prev);
                    ull nB = fma2(((k + 1) & 1) ? B.rp : B.rn, B.p_cur, B.p_prev);
                    A.p_prev = A.p_cur; A.p_cur = nA;
                    B.p_prev = B.p_cur; B.p_cur = nB;
                }
                A = An; B = Bn;
            }
            {
                // last dual pair (22,23) + single tail pair 24
                Chain C = seed_pair(sh_d2[warp][24], sh_p2[warp][24], sh_a2[warp][24],
                                    sh_r2[warp][24], wpos2, wm2);
                #pragma unroll
                for (int k = 0; k < KSTEPS; k++) {
                    acc[k] = add2(acc[k], A.p_cur);
                    acc[k] = add2(acc[k], B.p_cur);
                    ull nA = fma2(((k + 1) & 1) ? A.rp : A.rn, A.p_cur, A.p_prev);
                    ull nB = fma2(((k + 1) & 1) ? B.rp : B.rn, B.p_cur, B.p_prev);
                    A.p_prev = A.p_cur; A.p_cur = nA;
                    B.p_prev = B.p_cur; B.p_cur = nB;
                }
                #pragma unroll
                for (int k = 0; k < KSTEPS; k++) {
                    acc[k] = add2(acc[k], C.p_cur);
                    ull nC = fma2(((k + 1) & 1) ? C.rp : C.rn, C.p_cur, C.p_prev);
                    C.p_prev = C.p_cur; C.p_cur = nC;
                }
            }
        }

        // Stage windowed partials. Hann via stride-32 Chebyshev recurrence:
        // multiplier 2cos(pi/16) is an immediate (FFMA-imm, rt=1).
        {
            const int hbase = wh * HOPS + lane;     // window offset at k=0
            const float HSTEP = 6.283185307179586f / 1024.0f;
            float h1 = __cosf(HSTEP * (float)hbase);          // k = 0
            float h0 = __cosf(HSTEP * (float)(hbase - 32));   // k = -1
            #pragma unroll
            for (int k = 0; k < KSTEPS; k++) {
                float lo, hi;
                unpack2(acc[k], lo, hi);
                float s = lo + hi;
                float hann = fmaf(-0.5f, h1, 0.5f);
                // sigma_k = + for k%4 in {0,1}, - for {2,3}
                float v = (((k >> 1) & 1) == 0) ? (s * hann) : (s * (-hann));
                sh_part[warp][lane + 32 * k] = alive ? v : 0.0f;
                float h2 = fmaf(1.9615705608064609f, h1, -h0);  // FFMA-imm
                h0 = h1; h1 = h2;
            }
        }
        __syncthreads();

        // Combine 4 partials, single coalesced store.
        {
            float* outp = out + b * (TT * HOPS) + r * HOPS;
            #pragma unroll
            for (int i = threadIdx.x; i < HOPS; i += 128) {
                float v = (sh_part[0][i] + sh_part[1][i]) + (sh_part[2][i] + sh_part[3][i]);
                outp[i] = v;
            }
        }
        __syncthreads();   // protect sh_part before next region's staging
    }
}

extern "C" void kernel_launch(void* const* d_in, const int* in_sizes, int n_in,
                              void* d_out, int out_size) {
    const float* ampl  = (const float*)d_in[0];
    const float* phase = (const float*)d_in[1];
    const float* f0    = (const float*)d_in[2];
    float* out = (float*)d_out;

    sinstack_kernel<<<800, 128>>>(ampl, phase, f0, out);
}

// round 13
// speedup vs baseline: 1.0959x; 1.0959x over previous
#include <cuda_runtime.h>

#define HOPS 512
#define NHARM 100
#define TT 400
#define NHALF 50
#define NPAIR 25
#define KSTEPS 16   // window samples per lane (half window per warp)

typedef unsigned long long ull;

#define SIGN64 0x8000000080000000ull

struct ull2x { ull x, y; };

// ---- packed f32x2 helpers (sm_103a) ----
__device__ __forceinline__ ull pack2(float lo, float hi) {
    ull r; asm("mov.b64 %0, {%1, %2};" : "=l"(r) : "f"(lo), "f"(hi)); return r;
}
__device__ __forceinline__ void unpack2(ull v, float& lo, float& hi) {
    asm("mov.b64 {%0, %1}, %2;" : "=f"(lo), "=f"(hi) : "l"(v));
}
__device__ __forceinline__ ull fma2(ull a, ull b, ull c) {
    ull d; asm("fma.rn.f32x2 %0, %1, %2, %3;" : "=l"(d) : "l"(a), "l"(b), "l"(c)); return d;
}
__device__ __forceinline__ ull add2(ull a, ull b) {
    ull d; asm("add.rn.f32x2 %0, %1, %2;" : "=l"(d) : "l"(a), "l"(b)); return d;
}
__device__ __forceinline__ ull mul2(ull a, ull b) {
    ull d; asm("mul.rn.f32x2 %0, %1, %2;" : "=l"(d) : "l"(a), "l"(b)); return d;
}

struct Chain { ull p_prev, p_cur, rp, rn; };

// R7-exact seed arithmetic (codegen-fragile — do not restructure; R8/R9
// regressed). Params arrive as two LDS.128 loads: dp = {delta2, phase2},
// ar = {ampl2, 2cos(32*delta)2}.
__device__ __forceinline__ Chain seed_pair(ull2x dp, ull2x ar,
                                           ull wpos2, ull wm2) {
    ull x2  = fma2(wpos2, dp.x, dp.y);        // theta
    ull xm2 = fma2(wm2,   dp.x, dp.y);        // theta - D
    float xA, xB, mA, mB;
    unpack2(x2, xA, xB);
    unpack2(xm2, mA, mB);
    ull cth2  = pack2(__cosf(xA), __cosf(xB));
    ull cthm2 = pack2(__cosf(mA), __cosf(mB));

    Chain c;
    c.p_cur  = mul2(ar.x, cth2);              // +a*cos(th)
    c.p_prev = mul2(ar.x ^ SIGN64, cthm2);    // -a*cos(th-D)
    c.rp = ar.y;                              // +2cos(D) (precomputed)
    c.rn = ar.y ^ SIGN64;                     // -2cos(D)
    return c;
}

// Block = one 512-sample output region r of batch b. Contributors: frame t=r
// (window half 1) and frame t=r+1 (window half 0). 4 warps = 2 frames x 2
// harmonic halves; lane l owns region samples s = l + 32k, k=0..15.
// Dual packed Chebyshev chains, seeds software-pipelined one pair ahead.
// Hann via stride-32 Chebyshev recurrence with an immediate multiplier.
// Partials staged in shared; one coalesced STG.128 store per region.
__global__ __launch_bounds__(128, 7) void sinstack_kernel(
    const float* __restrict__ ampl,
    const float* __restrict__ phase,
    const float* __restrict__ f0,
    float* __restrict__ out)
{
    __shared__ __align__(16) ull2x sh_dp[4][NPAIR];  // {delta2, phase2}
    __shared__ __align__(16) ull2x sh_ar[4][NPAIR];  // {ampl2, r2}
    __shared__ __align__(16) float sh_part[4][512];

    const int warp = threadIdx.x >> 5;
    const int lane = threadIdx.x & 31;
    const int b = blockIdx.x / TT;
    const int r = blockIdx.x - b * TT;     // output region 0..399
    const int wh = 1 - (warp >> 1);        // warps 0,1: frame r (wh=1); 2,3: frame r+1 (wh=0)
    const int hh = warp & 1;               // harmonic half
    const int t  = r + (warp >> 1);        // frame index (may be TT: dead warp)
    const bool alive = (t < TT);

    if (alive) {
        const float K2PI_SR = 6.283185307179586f / 44100.0f;
        const int base = b * NHARM * TT + (hh * NHALF) * TT + t;
        float* fdp = (float*)&sh_dp[warp][0];   // per pair: [d0, d1, p0, p1]
        float* far_ = (float*)&sh_ar[warp][0];  // per pair: [a0, a1, r0, r1]
        for (int j = lane; j < NHALF; j += 32) {
            int idx = base + j * TT;
            int jp = j >> 1, sub = j & 1;
            float d = f0[idx] * K2PI_SR;
            fdp[jp * 4 + sub]     = d;
            fdp[jp * 4 + 2 + sub] = phase[idx];
            far_[jp * 4 + sub]     = ampl[idx];
            far_[jp * 4 + 2 + sub] = 2.0f * __cosf(32.0f * d);  // one-time MUFU
        }
    }
    __syncwarp();

    ull acc[KSTEPS];
    #pragma unroll
    for (int k = 0; k < KSTEPS; k++) acc[k] = 0ull;

    if (alive) {
        // window position of lane's k=0 sample: wh=1 -> lane; wh=0 -> lane-512
        const float wpos = (float)(lane + (wh ? 0 : -HOPS));
        const ull wpos2 = pack2(wpos, wpos);
        const ull wm2   = pack2(wpos - 32.0f, wpos - 32.0f);

        Chain A = seed_pair(sh_dp[warp][0], sh_ar[warp][0], wpos2, wm2);
        Chain B = seed_pair(sh_dp[warp][1], sh_ar[warp][1], wpos2, wm2);

        #pragma unroll 1
        for (int q = 0; q < 11; q++) {
            int j = 2 * q + 2;
            Chain An = seed_pair(sh_dp[warp][j],   sh_ar[warp][j],   wpos2, wm2);
            Chain Bn = seed_pair(sh_dp[warp][j+1], sh_ar[warp][j+1], wpos2, wm2);
            #pragma unroll
            for (int k = 0; k < KSTEPS; k++) {
                acc[k] = add2(acc[k], A.p_cur);
                acc[k] = add2(acc[k], B.p_cur);
                ull nA = fma2(((k + 1) & 1) ? A.rp : A.rn, A.p_cur, A.p_prev);
                ull nB = fma2(((k + 1) & 1) ? B.rp : B.rn, B.p_cur, B.p_prev);
                A.p_prev = A.p_cur; A.p_cur = nA;
                B.p_prev = B.p_cur; B.p_cur = nB;
            }
            A = An; B = Bn;
        }
        {
            // last dual pair (22,23) + single tail pair 24
            Chain C = seed_pair(sh_dp[warp][24], sh_ar[warp][24], wpos2, wm2);
            #pragma unroll
            for (int k = 0; k < KSTEPS; k++) {
                acc[k] = add2(acc[k], A.p_cur);
                acc[k] = add2(acc[k], B.p_cur);
                ull nA = fma2(((k + 1) & 1) ? A.rp : A.rn, A.p_cur, A.p_prev);
                ull nB = fma2(((k + 1) & 1) ? B.rp : B.rn, B.p_cur, B.p_prev);
                A.p_prev = A.p_cur; A.p_cur = nA;
                B.p_prev = B.p_cur; B.p_cur = nB;
            }
            #pragma unroll
            for (int k = 0; k < KSTEPS; k++) {
                acc[k] = add2(acc[k], C.p_cur);
                ull nC = fma2(((k + 1) & 1) ? C.rp : C.rn, C.p_cur, C.p_prev);
                C.p_prev = C.p_cur; C.p_cur = nC;
            }
        }
    }

    // Stage windowed partials. Hann via stride-32 Chebyshev recurrence:
    // multiplier 2cos(pi/16) is an immediate (FFMA-imm, rt=1).
    {
        const int hbase = wh * HOPS + lane;     // window offset at k=0
        const float HSTEP = 6.283185307179586f / 1024.0f;
        float h1 = __cosf(HSTEP * (float)hbase);          // k = 0
        float h0 = __cosf(HSTEP * (float)(hbase - 32));   // k = -1
        #pragma unroll
        for (int k = 0; k < KSTEPS; k++) {
            float lo, hi;
            unpack2(acc[k], lo, hi);
            float s = lo + hi;
            float hann = fmaf(-0.5f, h1, 0.5f);
            // sigma_k = + for k%4 in {0,1}, - for {2,3}
            float v = (((k >> 1) & 1) == 0) ? (s * hann) : (s * (-hann));
            sh_part[warp][lane + 32 * k] = alive ? v : 0.0f;
            float h2 = fmaf(1.9615705608064609f, h1, -h0);  // FFMA-imm
            h0 = h1; h1 = h2;
        }
    }
    __syncthreads();

    // Combine 4 partials with vector loads; one STG.128 per thread.
    {
        float4* outp = (float4*)(out + b * (TT * HOPS) + r * HOPS);
        int i = threadIdx.x;   // 128 threads x float4 = 512 samples
        float4 p0 = ((const float4*)&sh_part[0][0])[i];
        float4 p1 = ((const float4*)&sh_part[1][0])[i];
        float4 p2 = ((const float4*)&sh_part[2][0])[i];
        float4 p3 = ((const float4*)&sh_part[3][0])[i];
        float4 v;
        v.x = (p0.x + p1.x) + (p2.x + p3.x);
        v.y = (p0.y + p1.y) + (p2.y + p3.y);
        v.z = (p0.z + p1.z) + (p2.z + p3.z);
        v.w = (p0.w + p1.w) + (p2.w + p3.w);
        outp[i] = v;
    }
}

extern "C" void kernel_launch(void* const* d_in, const int* in_sizes, int n_in,
                              void* d_out, int out_size) {
    const float* ampl  = (const float*)d_in[0];
    const float* phase = (const float*)d_in[1];
    const float* f0    = (const float*)d_in[2];
    float* out = (float*)d_out;

    sinstack_kernel<<<1600, 128>>>(ampl, phase, f0, out);
}

// round 15
// speedup vs baseline: 1.1881x; 1.0841x over previous
#include <cuda_runtime.h>

#define HOPS 512
#define NHARM 100
#define TT 400
#define NHALF 50
#define NPAIR 25
#define KSTEPS 16   // window samples per lane (half window per warp)

typedef unsigned long long ull;

#define SIGN64 0x8000000080000000ull

// ---- packed f32x2 helpers (sm_103a) ----
__device__ __forceinline__ ull pack2(float lo, float hi) {
    ull r; asm("mov.b64 %0, {%1, %2};" : "=l"(r) : "f"(lo), "f"(hi)); return r;
}
__device__ __forceinline__ void unpack2(ull v, float& lo, float& hi) {
    asm("mov.b64 {%0, %1}, %2;" : "=f"(lo), "=f"(hi) : "l"(v));
}
__device__ __forceinline__ ull fma2(ull a, ull b, ull c) {
    ull d; asm("fma.rn.f32x2 %0, %1, %2, %3;" : "=l"(d) : "l"(a), "l"(b), "l"(c)); return d;
}
__device__ __forceinline__ ull add2(ull a, ull b) {
    ull d; asm("add.rn.f32x2 %0, %1, %2;" : "=l"(d) : "l"(a), "l"(b)); return d;
}
__device__ __forceinline__ ull mul2(ull a, ull b) {
    ull d; asm("mul.rn.f32x2 %0, %1, %2;" : "=l"(d) : "l"(a), "l"(b)); return d;
}

struct Chain { ull p_prev, p_cur, rp, rn; };

// R7/R11-exact seed: theta and theta-D via two fma2 against different wpos
// constants; r = 2cos(32*delta) precomputed in shared; negations are
// 64-bit XORs. (Codegen-fragile region — byte-identical to R11; every
// restructuring attempt, R8/R9/R13, regressed.)
__device__ __forceinline__ Chain seed_pair(ull dd, ull pp, ull aa, ull rp,
                                           ull wpos2, ull wm2) {
    ull x2  = fma2(wpos2, dd, pp);            // theta
    ull xm2 = fma2(wm2,   dd, pp);            // theta - D
    float xA, xB, mA, mB;
    unpack2(x2, xA, xB);
    unpack2(xm2, mA, mB);
    ull cth2  = pack2(__cosf(xA), __cosf(xB));
    ull cthm2 = pack2(__cosf(mA), __cosf(mB));

    Chain c;
    c.p_cur  = mul2(aa, cth2);                // +a*cos(th)
    c.p_prev = mul2(aa ^ SIGN64, cthm2);      // -a*cos(th-D)
    c.rp = rp;                                // +2cos(D) (precomputed)
    c.rn = rp ^ SIGN64;                       // -2cos(D)
    return c;
}

// Block = one 512-sample output region r of batch b. Contributors: frame t=r
// (window half 1) and frame t=r+1 (window half 0). 4 warps = 2 frames x 2
// harmonic halves; lane l owns region samples s = l + 32k, k=0..15.
// Dual packed Chebyshev chains, seeds software-pipelined one pair ahead.
// Hann via stride-32 Chebyshev recurrence with an immediate multiplier.
// Partials staged in shared; combined with float4 loads, one STG.128/thread.
__global__ __launch_bounds__(128, 7) void sinstack_kernel(
    const float* __restrict__ ampl,
    const float* __restrict__ phase,
    const float* __restrict__ f0,
    float* __restrict__ out)
{
    __shared__ ull sh_d2[4][NPAIR];
    __shared__ ull sh_p2[4][NPAIR];
    __shared__ ull sh_a2[4][NPAIR];
    __shared__ ull sh_r2[4][NPAIR];     // 2*cos(32*delta), precomputed
    __shared__ __align__(16) float sh_part[4][512];

    const int warp = threadIdx.x >> 5;
    const int lane = threadIdx.x & 31;
    const int b = blockIdx.x / TT;
    const int r = blockIdx.x - b * TT;     // output region 0..399
    const int wh = 1 - (warp >> 1);        // warps 0,1: frame r (wh=1); 2,3: frame r+1 (wh=0)
    const int hh = warp & 1;               // harmonic half
    const int t  = r + (warp >> 1);        // frame index (may be TT: dead warp)
    const bool alive = (t < TT);

    if (alive) {
        const float K2PI_SR = 6.283185307179586f / 44100.0f;
        const int base = b * NHARM * TT + (hh * NHALF) * TT + t;
        float* fd = (float*)&sh_d2[warp][0];
        float* fp = (float*)&sh_p2[warp][0];
        float* fa = (float*)&sh_a2[warp][0];
        float* fr = (float*)&sh_r2[warp][0];
        for (int j = lane; j < NHALF; j += 32) {
            int idx = base + j * TT;
            float d = f0[idx] * K2PI_SR;
            fd[j] = d;
            fp[j] = phase[idx];
            fa[j] = ampl[idx];
            fr[j] = 2.0f * __cosf(32.0f * d);   // one-time MUFU, off hot path
        }
    }
    __syncwarp();

    ull acc[KSTEPS];
    #pragma unroll
    for (int k = 0; k < KSTEPS; k++) acc[k] = 0ull;

    if (alive) {
        // window position of lane's k=0 sample: wh=1 -> lane; wh=0 -> lane-512
        const float wpos = (float)(lane + (wh ? 0 : -HOPS));
        const ull wpos2 = pack2(wpos, wpos);
        const ull wm2   = pack2(wpos - 32.0f, wpos - 32.0f);

        Chain A = seed_pair(sh_d2[warp][0], sh_p2[warp][0], sh_a2[warp][0],
                            sh_r2[warp][0], wpos2, wm2);
        Chain B = seed_pair(sh_d2[warp][1], sh_p2[warp][1], sh_a2[warp][1],
                            sh_r2[warp][1], wpos2, wm2);

        #pragma unroll 1
        for (int q = 0; q < 11; q++) {
            int j = 2 * q + 2;
            Chain An = seed_pair(sh_d2[warp][j], sh_p2[warp][j], sh_a2[warp][j],
                                 sh_r2[warp][j], wpos2, wm2);
            Chain Bn = seed_pair(sh_d2[warp][j+1], sh_p2[warp][j+1], sh_a2[warp][j+1],
                                 sh_r2[warp][j+1], wpos2, wm2);
            #pragma unroll
            for (int k = 0; k < KSTEPS; k++) {
                acc[k] = add2(acc[k], A.p_cur);
                acc[k] = add2(acc[k], B.p_cur);
                ull nA = fma2(((k + 1) & 1) ? A.rp : A.rn, A.p_cur, A.p_prev);
                ull nB = fma2(((k + 1) & 1) ? B.rp : B.rn, B.p_cur, B.p_prev);
                A.p_prev = A.p_cur; A.p_cur = nA;
                B.p_prev = B.p_cur; B.p_cur = nB;
            }
            A = An; B = Bn;
        }
        {
            // last dual pair (22,23) + single tail pair 24
            Chain C = seed_pair(sh_d2[warp][24], sh_p2[warp][24], sh_a2[warp][24],
                                sh_r2[warp][24], wpos2, wm2);
            #pragma unroll
            for (int k = 0; k < KSTEPS; k++) {
                acc[k] = add2(acc[k], A.p_cur);
                acc[k] = add2(acc[k], B.p_cur);
                ull nA = fma2(((k + 1) & 1) ? A.rp : A.rn, A.p_cur, A.p_prev);
                ull nB = fma2(((k + 1) & 1) ? B.rp : B.rn, B.p_cur, B.p_prev);
                A.p_prev = A.p_cur; A.p_cur = nA;
                B.p_prev = B.p_cur; B.p_cur = nB;
            }
            #pragma unroll
            for (int k = 0; k < KSTEPS; k++) {
                acc[k] = add2(acc[k], C.p_cur);
                ull nC = fma2(((k + 1) & 1) ? C.rp : C.rn, C.p_cur, C.p_prev);
                C.p_prev = C.p_cur; C.p_cur = nC;
            }
        }
    }

    // Stage windowed partials. Hann via stride-32 Chebyshev recurrence:
    // cos(HSTEP*(w0+32k)), multiplier 2cos(pi/16) is an immediate (rt=1 FFMA).
    {
        const int hbase = wh * HOPS + lane;     // window offset at k=0
        const float HSTEP = 6.283185307179586f / 1024.0f;
        float h1 = __cosf(HSTEP * (float)hbase);          // k = 0
        float h0 = __cosf(HSTEP * (float)(hbase - 32));   // k = -1
        #pragma unroll
        for (int k = 0; k < KSTEPS; k++) {
            float lo, hi;
            unpack2(acc[k], lo, hi);
            float s = lo + hi;
            float hann = fmaf(-0.5f, h1, 0.5f);
            // sigma_k = + for k%4 in {0,1}, - for {2,3}
            float v = (((k >> 1) & 1) == 0) ? (s * hann) : (s * (-hann));
            sh_part[warp][lane + 32 * k] = alive ? v : 0.0f;
            float h2 = fmaf(1.9615705608064609f, h1, -h0);  // FFMA-imm
            h0 = h1; h1 = h2;
        }
    }
    __syncthreads();

    // Combine 4 partials with vector loads; one STG.128 per thread.
    {
        float4* outp = (float4*)(out + b * (TT * HOPS) + r * HOPS);
        int i = threadIdx.x;   // 128 threads x float4 = 512 samples
        float4 p0 = ((const float4*)&sh_part[0][0])[i];
        float4 p1 = ((const float4*)&sh_part[1][0])[i];
        float4 p2 = ((const float4*)&sh_part[2][0])[i];
        float4 p3 = ((const float4*)&sh_part[3][0])[i];
        float4 v;
        v.x = (p0.x + p1.x) + (p2.x + p3.x);
        v.y = (p0.y + p1.y) + (p2.y + p3.y);
        v.z = (p0.z + p1.z) + (p2.z + p3.z);
        v.w = (p0.w + p1.w) + (p2.w + p3.w);
        outp[i] = v;
    }
}

extern "C" void kernel_launch(void* const* d_in, const int* in_sizes, int n_in,
                              void* d_out, int out_size) {
    const float* ampl  = (const float*)d_in[0];
    const float* phase = (const float*)d_in[1];
    const float* f0    = (const float*)d_in[2];
    float* out = (float*)d_out;

    sinstack_kernel<<<1600, 128>>>(ampl, phase, f0, out);
}